// round 14
// baseline (speedup 1.0000x reference)
#include <cuda_runtime.h>
#include <cuda_fp16.h>
#include <cstdint>
#include <cstddef>

#define DINLINE __device__ __forceinline__

// ----------------------------- problem sizes -------------------------------
static constexpr int NROWS = 8192;        // M
static constexpr int KIN   = 4096;        // K
static constexpr int NOUT  = 16384;       // N

// ----------------------------- GEMM tiling ---------------------------------
static constexpr int BM = 128;
static constexpr int BN = 128;            // 2 CTAs per SM
static constexpr int BK = 64;             // 64 halves = 128B rows
static constexpr int NKT = KIN / BK;      // 64 K-tiles
static constexpr int STAGES = 3;
static constexpr int NTHREADS = 256;      // 8 warps, 2 CTAs/SM = 16 warps/SM

static constexpr int A_STAGE = BM * 128;  // 16384 B
static constexpr int B_STAGE = BN * 128;  // 16384 B
static constexpr int SMEM_A = 0;
static constexpr int SMEM_B = SMEM_A + STAGES * A_STAGE;        // 49152
static constexpr int SMEM_BYTES = SMEM_B + STAGES * B_STAGE;    // 98304

// ----------------------------- device scratch ------------------------------
__device__ unsigned short g_tw[(size_t)NOUT * KIN];   // ternary W as fp16 bits
__device__ unsigned short g_xh[(size_t)NROWS * KIN];  // x as fp16 bits
__device__ float g_partials[2048];

// ----------------------------- ptx helpers ---------------------------------
DINLINE uint32_t smem_u32(const void* p) {
    uint32_t a;
    asm("{ .reg .u64 t; cvta.to.shared.u64 t, %1; cvt.u32.u64 %0, t; }" : "=r"(a) : "l"(p));
    return a;
}
DINLINE void cp_async16(uint32_t dst, const void* src) {
    asm volatile("cp.async.cg.shared.global [%0], [%1], 16;" :: "r"(dst), "l"(src));
}
#define CP_COMMIT() asm volatile("cp.async.commit_group;" ::: "memory")
#define CP_WAIT1()  asm volatile("cp.async.wait_group 1;" ::: "memory")

DINLINE void ldsm4(uint32_t* r, uint32_t addr) {
    asm volatile("ldmatrix.sync.aligned.m8n8.x4.shared.b16 {%0,%1,%2,%3}, [%4];"
                 : "=r"(r[0]), "=r"(r[1]), "=r"(r[2]), "=r"(r[3]) : "r"(addr));
}
DINLINE void mma16816(float* d, const uint32_t* a, uint32_t b0, uint32_t b1) {
    asm volatile(
        "mma.sync.aligned.m16n8k16.row.col.f32.f16.f16.f32 "
        "{%0,%1,%2,%3}, {%4,%5,%6,%7}, {%8,%9}, {%0,%1,%2,%3};"
        : "+f"(d[0]), "+f"(d[1]), "+f"(d[2]), "+f"(d[3])
        : "r"(a[0]), "r"(a[1]), "r"(a[2]), "r"(a[3]), "r"(b0), "r"(b1));
}

// ----------------------------- preprocessing -------------------------------
__global__ void absum_kernel(const float* __restrict__ w) {
    const int n4 = (int)((size_t)NOUT * KIN / 4);
    const float4* w4 = (const float4*)w;
    float s = 0.f;
    for (int i = blockIdx.x * 256 + threadIdx.x; i < n4; i += 2048 * 256) {
        float4 v = w4[i];
        s += fabsf(v.x) + fabsf(v.y) + fabsf(v.z) + fabsf(v.w);
    }
    __shared__ float red[256];
    red[threadIdx.x] = s;
    __syncthreads();
    for (int o = 128; o; o >>= 1) {
        if (threadIdx.x < o) red[threadIdx.x] += red[threadIdx.x + o];
        __syncthreads();
    }
    if (threadIdx.x == 0) g_partials[blockIdx.x] = red[0];
}

// Combined: per-block threshold reduction, then ternarize W and halve x.
__global__ void prep_kernel(const float* __restrict__ w, const float* __restrict__ x) {
    __shared__ double red[256];
    double s = 0.0;
    for (int i = threadIdx.x; i < 2048; i += 256) s += (double)g_partials[i];
    red[threadIdx.x] = s;
    __syncthreads();
    for (int o = 128; o; o >>= 1) {
        if (threadIdx.x < o) red[threadIdx.x] += red[threadIdx.x + o];
        __syncthreads();
    }
    const float t = (float)(0.5 * red[0] / (double)((size_t)NOUT * KIN));

    // ternarize W -> fp16 {0, +-1}
    const int n4w = (int)((size_t)NOUT * KIN / 4);
    const float4* w4 = (const float4*)w;
    uint2* dw = (uint2*)g_tw;
    for (int i = blockIdx.x * 256 + threadIdx.x; i < n4w; i += 4096 * 256) {
        float4 v = w4[i];
        uint32_t b0 = (fabsf(v.x) >= t) ? (0x3C00u | ((__float_as_uint(v.x) >> 16) & 0x8000u)) : 0u;
        uint32_t b1 = (fabsf(v.y) >= t) ? (0x3C00u | ((__float_as_uint(v.y) >> 16) & 0x8000u)) : 0u;
        uint32_t b2 = (fabsf(v.z) >= t) ? (0x3C00u | ((__float_as_uint(v.z) >> 16) & 0x8000u)) : 0u;
        uint32_t b3 = (fabsf(v.w) >= t) ? (0x3C00u | ((__float_as_uint(v.w) >> 16) & 0x8000u)) : 0u;
        uint2 u;
        u.x = b0 | (b1 << 16);
        u.y = b2 | (b3 << 16);
        dw[i] = u;
    }

    // x -> fp16
    const int n4x = (int)((size_t)NROWS * KIN / 4);
    const float4* x4 = (const float4*)x;
    uint2* dx = (uint2*)g_xh;
    for (int i = blockIdx.x * 256 + threadIdx.x; i < n4x; i += 4096 * 256) {
        float4 v = x4[i];
        __half2 h01 = __floats2half2_rn(v.x, v.y);
        __half2 h23 = __floats2half2_rn(v.z, v.w);
        uint2 u;
        u.x = *(uint32_t*)&h01;
        u.y = *(uint32_t*)&h23;
        dx[i] = u;
    }
}

// tiny dummy so the GEMM is the 4th launch in the stream (ncu -s alignment)
__global__ void dummy_kernel() { g_partials[0] = 0.f; }

// ----------------------------- GEMM ----------------------------------------
// smem: row-major [rows][64 halves] = 128B rows, 16B chunk c swizzled to
// c ^ (row & 7). cp.async stores and all ldmatrix phases conflict-free.
DINLINE void issue_stage(int kt, int fs, int tid, uint32_t sb,
                         const char* gA, const char* gB) {
    const uint32_t adst = sb + SMEM_A + fs * A_STAGE;
    const uint32_t bdst = sb + SMEM_B + fs * B_STAGE;
    const char* asrc = gA + kt * 128;
    const char* bsrc = gB + kt * 128;
    #pragma unroll
    for (int j = 0; j < 4; j++) {               // A: 1024 chunks
        int ci = tid + NTHREADS * j;
        int row = ci >> 3, c = ci & 7;
        cp_async16(adst + row * 128 + ((c ^ (row & 7)) << 4),
                   asrc + (size_t)row * 8192 + c * 16);
    }
    #pragma unroll
    for (int j = 0; j < 4; j++) {               // B: 1024 chunks
        int ci = tid + NTHREADS * j;
        int row = ci >> 3, c = ci & 7;
        cp_async16(bdst + row * 128 + ((c ^ (row & 7)) << 4),
                   bsrc + (size_t)row * 8192 + c * 16);
    }
}

// One K-tile with compile-time stage constants (st = read stage, fs = fill stage).
DINLINE void tile_body(int kt, int st, int fs, int tid, uint32_t sb,
                       uint32_t aoff, uint32_t boff,
                       const char* gA, const char* gB, float acc[2][8][4]) {
    const uint32_t abase = sb + SMEM_A + st * A_STAGE + aoff;
    const uint32_t bbase = sb + SMEM_B + st * B_STAGE + boff;

    CP_WAIT1();
    __syncthreads();

    // k-step 0 fragments FIRST: feed the tensor pipe right after the barrier
    uint32_t aa[2][4], bb[4][4];
    #pragma unroll
    for (int mt = 0; mt < 2; mt++) ldsm4(aa[mt], abase + mt * 2048);
    #pragma unroll
    for (int nt = 0; nt < 4; nt++) ldsm4(bb[nt], bbase + nt * 2048);

    // cp.async burst for stage kt+2 rides under the LDSM->MMA latency
    if (kt + 2 < NKT) issue_stage(kt + 2, fs, tid, sb, gA, gB);
    CP_COMMIT();

    // j = 0 MMAs
    #pragma unroll
    for (int mt = 0; mt < 2; mt++)
        #pragma unroll
        for (int nt = 0; nt < 8; nt++) {
            const int g = nt >> 1;
            if ((nt & 1) == 0) mma16816(acc[mt][nt], aa[mt], bb[g][0], bb[g][2]);
            else               mma16816(acc[mt][nt], aa[mt], bb[g][1], bb[g][3]);
        }

    // j = 1..3
    #pragma unroll
    for (int j = 1; j < 4; j++) {
        const uint32_t x = (uint32_t)(j << 5);
        #pragma unroll
        for (int mt = 0; mt < 2; mt++) ldsm4(aa[mt], (abase + mt * 2048) ^ x);
        #pragma unroll
        for (int nt = 0; nt < 4; nt++) ldsm4(bb[nt], (bbase + nt * 2048) ^ x);
        #pragma unroll
        for (int mt = 0; mt < 2; mt++)
            #pragma unroll
            for (int nt = 0; nt < 8; nt++) {
                const int g = nt >> 1;
                if ((nt & 1) == 0) mma16816(acc[mt][nt], aa[mt], bb[g][0], bb[g][2]);
                else               mma16816(acc[mt][nt], aa[mt], bb[g][1], bb[g][3]);
            }
    }
}

__global__ void __launch_bounds__(NTHREADS, 2)
gemm_kernel(const float* __restrict__ bias, float* __restrict__ out) {
    extern __shared__ char smem[];
    const uint32_t sb = smem_u32(smem);
    const int tid = threadIdx.x, wid = tid >> 5, lid = tid & 31;

    // supertile mapping: 8 M-tiles x 128 N-tiles groups (8 groups of 1024)
    const int bid = blockIdx.x;
    const int grp = bid >> 10, rem = bid & 1023;
    const int mt_ = (grp << 3) | (rem & 7);
    const int nt_ = rem >> 3;
    const int m0 = mt_ * BM, n0 = nt_ * BN;

    const char* gA = (const char*)g_xh + (size_t)m0 * (KIN * 2);
    const char* gB = (const char*)g_tw + (size_t)n0 * (KIN * 2);

    // warp layout: 4 (M) x 2 (N), warp tile 32x64
    const int wm = wid & 3, wn = wid >> 2;

    // per-thread ldmatrix base offsets (swizzled, k-step 0)
    const int rlo = lid & 15, hh = lid >> 4;
    const int rowA = wm * 32 + rlo;
    const uint32_t aoff = (uint32_t)(rowA * 128 + ((hh ^ (rowA & 7)) << 4));
    const int rowB = wn * 64 + rlo;
    const uint32_t boff = (uint32_t)(rowB * 128 + ((hh ^ (rowB & 7)) << 4));

    float acc[2][8][4];
    #pragma unroll
    for (int i = 0; i < 2; i++)
        #pragma unroll
        for (int j = 0; j < 8; j++)
            #pragma unroll
            for (int q = 0; q < 4; q++) acc[i][j][q] = 0.f;

    // prologue: stages 0,1
    issue_stage(0, 0, tid, sb, gA, gB); CP_COMMIT();
    issue_stage(1, 1, tid, sb, gA, gB); CP_COMMIT();

    // 63 tiles = 21 triples with literal stage constants, then 1 tail tile.
    #pragma unroll 1
    for (int base = 0; base < NKT - 1; base += 3) {
        tile_body(base + 0, 0, 2, tid, sb, aoff, boff, gA, gB, acc);
        tile_body(base + 1, 1, 0, tid, sb, aoff, boff, gA, gB, acc);
        tile_body(base + 2, 2, 1, tid, sb, aoff, boff, gA, gB, acc);
    }
    tile_body(NKT - 1, 0, 2, tid, sb, aoff, boff, gA, gB, acc);  // kt=63, st=63%3=0

    // ----------------------------- epilogue --------------------------------
    const int rbase = m0 + wm * 32 + (lid >> 2);
    const int cbase = n0 + wn * 64 + (lid & 3) * 2;
    #pragma unroll
    for (int nt = 0; nt < 8; nt++) {
        const int col = cbase + nt * 8;
        const float2 bv = *(const float2*)(bias + col);
        #pragma unroll
        for (int mt = 0; mt < 2; mt++) {
            const int r0 = rbase + mt * 16;
            float2 v;
            v.x = acc[mt][nt][0] + bv.x;
            v.y = acc[mt][nt][1] + bv.y;
            *(float2*)(out + (size_t)r0 * NOUT + col) = v;
            v.x = acc[mt][nt][2] + bv.x;
            v.y = acc[mt][nt][3] + bv.y;
            *(float2*)(out + (size_t)(r0 + 8) * NOUT + col) = v;
        }
    }
}

// ----------------------------- launch --------------------------------------
extern "C" void kernel_launch(void* const* d_in, const int* in_sizes, int n_in,
                              void* d_out, int out_size) {
    const float* x    = (const float*)d_in[0];   // [8192, 4096]
    const float* w    = (const float*)d_in[1];   // [16384, 4096]
    const float* bias = (const float*)d_in[2];   // [16384]
    float* out        = (float*)d_out;           // [8192, 16384]

    cudaFuncSetAttribute(gemm_kernel, cudaFuncAttributeMaxDynamicSharedMemorySize, SMEM_BYTES);

    absum_kernel<<<2048, 256>>>(w);
    prep_kernel<<<4096, 256>>>(w, x);
    dummy_kernel<<<1, 1>>>();

    const int grid = (NROWS / BM) * (NOUT / BN);  // 64 * 128 = 8192
    gemm_kernel<<<grid, NTHREADS, SMEM_BYTES>>>(bias, out);
}

// round 15
// speedup vs baseline: 1.0002x; 1.0002x over previous
#include <cuda_runtime.h>
#include <cuda_fp16.h>
#include <cstdint>
#include <cstddef>

#define DINLINE __device__ __forceinline__

// ----------------------------- problem sizes -------------------------------
static constexpr int NROWS = 8192;        // M
static constexpr int KIN   = 4096;        // K
static constexpr int NOUT  = 16384;       // N

// ----------------------------- GEMM tiling ---------------------------------
static constexpr int BM = 128;
static constexpr int BN = 128;            // 2 CTAs per SM
static constexpr int BK = 64;             // 64 halves = 128B rows
static constexpr int NKT = KIN / BK;      // 64 K-tiles
static constexpr int STAGES = 3;
static constexpr int NTHREADS = 256;      // 8 warps, 2 CTAs/SM = 16 warps/SM

static constexpr int A_STAGE = BM * 128;  // 16384 B
static constexpr int B_STAGE = BN * 128;  // 16384 B
static constexpr int SMEM_A = 0;
static constexpr int SMEM_B = SMEM_A + STAGES * A_STAGE;        // 49152
static constexpr int SMEM_BYTES = SMEM_B + STAGES * B_STAGE;    // 98304

// ----------------------------- device scratch ------------------------------
__device__ unsigned short g_tw[(size_t)NOUT * KIN];   // ternary W as fp16 bits
__device__ unsigned short g_xh[(size_t)NROWS * KIN];  // x as fp16 bits
__device__ float g_partials[2048];

// ----------------------------- ptx helpers ---------------------------------
DINLINE uint32_t smem_u32(const void* p) {
    uint32_t a;
    asm("{ .reg .u64 t; cvta.to.shared.u64 t, %1; cvt.u32.u64 %0, t; }" : "=r"(a) : "l"(p));
    return a;
}
DINLINE void cp_async16(uint32_t dst, const void* src) {
    asm volatile("cp.async.cg.shared.global [%0], [%1], 16;" :: "r"(dst), "l"(src));
}
#define CP_COMMIT() asm volatile("cp.async.commit_group;" ::: "memory")
#define CP_WAIT1()  asm volatile("cp.async.wait_group 1;" ::: "memory")

DINLINE void ldsm4(uint32_t* r, uint32_t addr) {
    asm volatile("ldmatrix.sync.aligned.m8n8.x4.shared.b16 {%0,%1,%2,%3}, [%4];"
                 : "=r"(r[0]), "=r"(r[1]), "=r"(r[2]), "=r"(r[3]) : "r"(addr));
}
DINLINE void mma16816(float* d, const uint32_t* a, uint32_t b0, uint32_t b1) {
    asm volatile(
        "mma.sync.aligned.m16n8k16.row.col.f32.f16.f16.f32 "
        "{%0,%1,%2,%3}, {%4,%5,%6,%7}, {%8,%9}, {%0,%1,%2,%3};"
        : "+f"(d[0]), "+f"(d[1]), "+f"(d[2]), "+f"(d[3])
        : "r"(a[0]), "r"(a[1]), "r"(a[2]), "r"(a[3]), "r"(b0), "r"(b1));
}

// ----------------------------- preprocessing -------------------------------
__global__ void absum_kernel(const float* __restrict__ w) {
    const int n4 = (int)((size_t)NOUT * KIN / 4);
    const float4* w4 = (const float4*)w;
    float s = 0.f;
    for (int i = blockIdx.x * 256 + threadIdx.x; i < n4; i += 2048 * 256) {
        float4 v = w4[i];
        s += fabsf(v.x) + fabsf(v.y) + fabsf(v.z) + fabsf(v.w);
    }
    __shared__ float red[256];
    red[threadIdx.x] = s;
    __syncthreads();
    for (int o = 128; o; o >>= 1) {
        if (threadIdx.x < o) red[threadIdx.x] += red[threadIdx.x + o];
        __syncthreads();
    }
    if (threadIdx.x == 0) g_partials[blockIdx.x] = red[0];
}

// Combined: per-block threshold reduction, then ternarize W and halve x.
__global__ void prep_kernel(const float* __restrict__ w, const float* __restrict__ x) {
    __shared__ double red[256];
    double s = 0.0;
    for (int i = threadIdx.x; i < 2048; i += 256) s += (double)g_partials[i];
    red[threadIdx.x] = s;
    __syncthreads();
    for (int o = 128; o; o >>= 1) {
        if (threadIdx.x < o) red[threadIdx.x] += red[threadIdx.x + o];
        __syncthreads();
    }
    const float t = (float)(0.5 * red[0] / (double)((size_t)NOUT * KIN));

    // ternarize W -> fp16 {0, +-1}
    const int n4w = (int)((size_t)NOUT * KIN / 4);
    const float4* w4 = (const float4*)w;
    uint2* dw = (uint2*)g_tw;
    for (int i = blockIdx.x * 256 + threadIdx.x; i < n4w; i += 4096 * 256) {
        float4 v = w4[i];
        uint32_t b0 = (fabsf(v.x) >= t) ? (0x3C00u | ((__float_as_uint(v.x) >> 16) & 0x8000u)) : 0u;
        uint32_t b1 = (fabsf(v.y) >= t) ? (0x3C00u | ((__float_as_uint(v.y) >> 16) & 0x8000u)) : 0u;
        uint32_t b2 = (fabsf(v.z) >= t) ? (0x3C00u | ((__float_as_uint(v.z) >> 16) & 0x8000u)) : 0u;
        uint32_t b3 = (fabsf(v.w) >= t) ? (0x3C00u | ((__float_as_uint(v.w) >> 16) & 0x8000u)) : 0u;
        uint2 u;
        u.x = b0 | (b1 << 16);
        u.y = b2 | (b3 << 16);
        dw[i] = u;
    }

    // x -> fp16
    const int n4x = (int)((size_t)NROWS * KIN / 4);
    const float4* x4 = (const float4*)x;
    uint2* dx = (uint2*)g_xh;
    for (int i = blockIdx.x * 256 + threadIdx.x; i < n4x; i += 4096 * 256) {
        float4 v = x4[i];
        __half2 h01 = __floats2half2_rn(v.x, v.y);
        __half2 h23 = __floats2half2_rn(v.z, v.w);
        uint2 u;
        u.x = *(uint32_t*)&h01;
        u.y = *(uint32_t*)&h23;
        dx[i] = u;
    }
}

// tiny dummy so the GEMM is the 4th launch in the stream (ncu -s alignment)
__global__ void dummy_kernel() { g_partials[0] = 0.f; }

// ----------------------------- GEMM ----------------------------------------
// smem: row-major [rows][64 halves] = 128B rows, 16B chunk c swizzled to
// c ^ (row & 7). cp.async stores and all ldmatrix phases conflict-free.
DINLINE void issue_stage(int kt, int fs, int tid, uint32_t sb,
                         const char* gA, const char* gB) {
    const uint32_t adst = sb + SMEM_A + fs * A_STAGE;
    const uint32_t bdst = sb + SMEM_B + fs * B_STAGE;
    const char* asrc = gA + kt * 128;
    const char* bsrc = gB + kt * 128;
    #pragma unroll
    for (int j = 0; j < 4; j++) {               // A: 1024 chunks
        int ci = tid + NTHREADS * j;
        int row = ci >> 3, c = ci & 7;
        cp_async16(adst + row * 128 + ((c ^ (row & 7)) << 4),
                   asrc + (size_t)row * 8192 + c * 16);
    }
    #pragma unroll
    for (int j = 0; j < 4; j++) {               // B: 1024 chunks
        int ci = tid + NTHREADS * j;
        int row = ci >> 3, c = ci & 7;
        cp_async16(bdst + row * 128 + ((c ^ (row & 7)) << 4),
                   bsrc + (size_t)row * 8192 + c * 16);
    }
}

// One K-tile with compile-time stage constants (st = read stage, fs = fill stage).
DINLINE void tile_body(int kt, int st, int fs, int tid, uint32_t sb,
                       uint32_t aoff, uint32_t boff,
                       const char* gA, const char* gB, float acc[2][8][4]) {
    const uint32_t abase = sb + SMEM_A + st * A_STAGE + aoff;
    const uint32_t bbase = sb + SMEM_B + st * B_STAGE + boff;

    CP_WAIT1();
    __syncthreads();

    // k-step 0 fragments FIRST: feed the tensor pipe right after the barrier
    uint32_t aa[2][4], bb[4][4];
    #pragma unroll
    for (int mt = 0; mt < 2; mt++) ldsm4(aa[mt], abase + mt * 2048);
    #pragma unroll
    for (int nt = 0; nt < 4; nt++) ldsm4(bb[nt], bbase + nt * 2048);

    // cp.async burst for stage kt+2 rides under the LDSM->MMA latency
    if (kt + 2 < NKT) issue_stage(kt + 2, fs, tid, sb, gA, gB);
    CP_COMMIT();

    // j = 0 MMAs
    #pragma unroll
    for (int mt = 0; mt < 2; mt++)
        #pragma unroll
        for (int nt = 0; nt < 8; nt++) {
            const int g = nt >> 1;
            if ((nt & 1) == 0) mma16816(acc[mt][nt], aa[mt], bb[g][0], bb[g][2]);
            else               mma16816(acc[mt][nt], aa[mt], bb[g][1], bb[g][3]);
        }

    // j = 1..3
    #pragma unroll
    for (int j = 1; j < 4; j++) {
        const uint32_t x = (uint32_t)(j << 5);
        #pragma unroll
        for (int mt = 0; mt < 2; mt++) ldsm4(aa[mt], (abase + mt * 2048) ^ x);
        #pragma unroll
        for (int nt = 0; nt < 4; nt++) ldsm4(bb[nt], (bbase + nt * 2048) ^ x);
        #pragma unroll
        for (int mt = 0; mt < 2; mt++)
            #pragma unroll
            for (int nt = 0; nt < 8; nt++) {
                const int g = nt >> 1;
                if ((nt & 1) == 0) mma16816(acc[mt][nt], aa[mt], bb[g][0], bb[g][2]);
                else               mma16816(acc[mt][nt], aa[mt], bb[g][1], bb[g][3]);
            }
    }
}

__global__ void __launch_bounds__(NTHREADS, 2)
gemm_kernel(const float* __restrict__ bias, float* __restrict__ out) {
    extern __shared__ char smem[];
    const uint32_t sb = smem_u32(smem);
    const int tid = threadIdx.x, wid = tid >> 5, lid = tid & 31;

    // supertile mapping: 8 M-tiles x 128 N-tiles groups (8 groups of 1024)
    const int bid = blockIdx.x;
    const int grp = bid >> 10, rem = bid & 1023;
    const int mt_ = (grp << 3) | (rem & 7);
    const int nt_ = rem >> 3;
    const int m0 = mt_ * BM, n0 = nt_ * BN;

    const char* gA = (const char*)g_xh + (size_t)m0 * (KIN * 2);
    const char* gB = (const char*)g_tw + (size_t)n0 * (KIN * 2);

    // warp layout: 4 (M) x 2 (N), warp tile 32x64
    const int wm = wid & 3, wn = wid >> 2;

    // per-thread ldmatrix base offsets (swizzled, k-step 0)
    const int rlo = lid & 15, hh = lid >> 4;
    const int rowA = wm * 32 + rlo;
    const uint32_t aoff = (uint32_t)(rowA * 128 + ((hh ^ (rowA & 7)) << 4));
    const int rowB = wn * 64 + rlo;
    const uint32_t boff = (uint32_t)(rowB * 128 + ((hh ^ (rowB & 7)) << 4));

    float acc[2][8][4];
    #pragma unroll
    for (int i = 0; i < 2; i++)
        #pragma unroll
        for (int j = 0; j < 8; j++)
            #pragma unroll
            for (int q = 0; q < 4; q++) acc[i][j][q] = 0.f;

    // prologue: stages 0,1
    issue_stage(0, 0, tid, sb, gA, gB); CP_COMMIT();
    issue_stage(1, 1, tid, sb, gA, gB); CP_COMMIT();

    // 63 tiles = 21 triples with literal stage constants, then 1 tail tile.
    #pragma unroll 1
    for (int base = 0; base < NKT - 1; base += 3) {
        tile_body(base + 0, 0, 2, tid, sb, aoff, boff, gA, gB, acc);
        tile_body(base + 1, 1, 0, tid, sb, aoff, boff, gA, gB, acc);
        tile_body(base + 2, 2, 1, tid, sb, aoff, boff, gA, gB, acc);
    }
    tile_body(NKT - 1, 0, 2, tid, sb, aoff, boff, gA, gB, acc);  // kt=63, st=63%3=0

    // ----------------------------- epilogue --------------------------------
    const int rbase = m0 + wm * 32 + (lid >> 2);
    const int cbase = n0 + wn * 64 + (lid & 3) * 2;
    #pragma unroll
    for (int nt = 0; nt < 8; nt++) {
        const int col = cbase + nt * 8;
        const float2 bv = *(const float2*)(bias + col);
        #pragma unroll
        for (int mt = 0; mt < 2; mt++) {
            const int r0 = rbase + mt * 16;
            float2 v;
            v.x = acc[mt][nt][0] + bv.x;
            v.y = acc[mt][nt][1] + bv.y;
            *(float2*)(out + (size_t)r0 * NOUT + col) = v;
            v.x = acc[mt][nt][2] + bv.x;
            v.y = acc[mt][nt][3] + bv.y;
            *(float2*)(out + (size_t)(r0 + 8) * NOUT + col) = v;
        }
    }
}

// ----------------------------- launch --------------------------------------
extern "C" void kernel_launch(void* const* d_in, const int* in_sizes, int n_in,
                              void* d_out, int out_size) {
    const float* x    = (const float*)d_in[0];   // [8192, 4096]
    const float* w    = (const float*)d_in[1];   // [16384, 4096]
    const float* bias = (const float*)d_in[2];   // [16384]
    float* out        = (float*)d_out;           // [8192, 16384]

    cudaFuncSetAttribute(gemm_kernel, cudaFuncAttributeMaxDynamicSharedMemorySize, SMEM_BYTES);

    absum_kernel<<<2048, 256>>>(w);
    prep_kernel<<<4096, 256>>>(w, x);
    dummy_kernel<<<1, 1>>>();

    const int grid = (NROWS / BM) * (NOUT / BN);  // 64 * 128 = 8192
    gemm_kernel<<<grid, NTHREADS, SMEM_BYTES>>>(bias, out);
}

// round 16
// speedup vs baseline: 1.0953x; 1.0950x over previous
#include <cuda_runtime.h>
#include <cuda_fp16.h>
#include <cstdint>
#include <cstddef>

#define DINLINE __device__ __forceinline__

// ----------------------------- problem sizes -------------------------------
static constexpr int NROWS = 8192;        // M
static constexpr int KIN   = 4096;        // K
static constexpr int NOUT  = 16384;       // N

// ----------------------------- GEMM tiling ---------------------------------
static constexpr int BM = 128;
static constexpr int BN = 128;            // 2 CTAs per SM
static constexpr int BK = 64;             // 64 halves = 128B rows
static constexpr int NKT = KIN / BK;      // 64 K-tiles
static constexpr int STAGES = 3;
static constexpr int NTHREADS = 256;      // 8 warps, 2 CTAs/SM = 16 warps/SM

static constexpr int A_STAGE = BM * 128;  // 16384 B
static constexpr int B_STAGE = BN * 128;  // 16384 B
static constexpr int SMEM_A = 0;
static constexpr int SMEM_B = SMEM_A + STAGES * A_STAGE;        // 49152
static constexpr int SMEM_BYTES = SMEM_B + STAGES * B_STAGE;    // 98304

// ----------------------------- device scratch ------------------------------
__device__ unsigned short g_tw[(size_t)NOUT * KIN];   // ternary W as fp16 bits
__device__ unsigned short g_xh[(size_t)NROWS * KIN];  // x as fp16 bits
__device__ float g_partials[2048];

// ----------------------------- ptx helpers ---------------------------------
DINLINE uint32_t smem_u32(const void* p) {
    uint32_t a;
    asm("{ .reg .u64 t; cvta.to.shared.u64 t, %1; cvt.u32.u64 %0, t; }" : "=r"(a) : "l"(p));
    return a;
}
DINLINE void cp_async16(uint32_t dst, const void* src) {
    asm volatile("cp.async.cg.shared.global [%0], [%1], 16;" :: "r"(dst), "l"(src));
}
#define CP_COMMIT() asm volatile("cp.async.commit_group;" ::: "memory")
#define CP_WAIT1()  asm volatile("cp.async.wait_group 1;" ::: "memory")

DINLINE void ldsm4(uint32_t* r, uint32_t addr) {
    asm volatile("ldmatrix.sync.aligned.m8n8.x4.shared.b16 {%0,%1,%2,%3}, [%4];"
                 : "=r"(r[0]), "=r"(r[1]), "=r"(r[2]), "=r"(r[3]) : "r"(addr));
}
DINLINE void mma16816(float* d, const uint32_t* a, uint32_t b0, uint32_t b1) {
    asm volatile(
        "mma.sync.aligned.m16n8k16.row.col.f32.f16.f16.f32 "
        "{%0,%1,%2,%3}, {%4,%5,%6,%7}, {%8,%9}, {%0,%1,%2,%3};"
        : "+f"(d[0]), "+f"(d[1]), "+f"(d[2]), "+f"(d[3])
        : "r"(a[0]), "r"(a[1]), "r"(a[2]), "r"(a[3]), "r"(b0), "r"(b1));
}

// ----------------------------- preprocessing -------------------------------
__global__ void absum_kernel(const float* __restrict__ w) {
    const int n4 = (int)((size_t)NOUT * KIN / 4);
    const float4* w4 = (const float4*)w;
    float s = 0.f;
    for (int i = blockIdx.x * 256 + threadIdx.x; i < n4; i += 2048 * 256) {
        float4 v = w4[i];
        s += fabsf(v.x) + fabsf(v.y) + fabsf(v.z) + fabsf(v.w);
    }
    __shared__ float red[256];
    red[threadIdx.x] = s;
    __syncthreads();
    for (int o = 128; o; o >>= 1) {
        if (threadIdx.x < o) red[threadIdx.x] += red[threadIdx.x + o];
        __syncthreads();
    }
    if (threadIdx.x == 0) g_partials[blockIdx.x] = red[0];
}

// Combined: per-block threshold reduction, then ternarize W and halve x.
__global__ void prep_kernel(const float* __restrict__ w, const float* __restrict__ x) {
    __shared__ double red[256];
    double s = 0.0;
    for (int i = threadIdx.x; i < 2048; i += 256) s += (double)g_partials[i];
    red[threadIdx.x] = s;
    __syncthreads();
    for (int o = 128; o; o >>= 1) {
        if (threadIdx.x < o) red[threadIdx.x] += red[threadIdx.x + o];
        __syncthreads();
    }
    const float t = (float)(0.5 * red[0] / (double)((size_t)NOUT * KIN));

    // ternarize W -> fp16 {0, +-1}
    const int n4w = (int)((size_t)NOUT * KIN / 4);
    const float4* w4 = (const float4*)w;
    uint2* dw = (uint2*)g_tw;
    for (int i = blockIdx.x * 256 + threadIdx.x; i < n4w; i += 4096 * 256) {
        float4 v = w4[i];
        uint32_t b0 = (fabsf(v.x) >= t) ? (0x3C00u | ((__float_as_uint(v.x) >> 16) & 0x8000u)) : 0u;
        uint32_t b1 = (fabsf(v.y) >= t) ? (0x3C00u | ((__float_as_uint(v.y) >> 16) & 0x8000u)) : 0u;
        uint32_t b2 = (fabsf(v.z) >= t) ? (0x3C00u | ((__float_as_uint(v.z) >> 16) & 0x8000u)) : 0u;
        uint32_t b3 = (fabsf(v.w) >= t) ? (0x3C00u | ((__float_as_uint(v.w) >> 16) & 0x8000u)) : 0u;
        uint2 u;
        u.x = b0 | (b1 << 16);
        u.y = b2 | (b3 << 16);
        dw[i] = u;
    }

    // x -> fp16
    const int n4x = (int)((size_t)NROWS * KIN / 4);
    const float4* x4 = (const float4*)x;
    uint2* dx = (uint2*)g_xh;
    for (int i = blockIdx.x * 256 + threadIdx.x; i < n4x; i += 4096 * 256) {
        float4 v = x4[i];
        __half2 h01 = __floats2half2_rn(v.x, v.y);
        __half2 h23 = __floats2half2_rn(v.z, v.w);
        uint2 u;
        u.x = *(uint32_t*)&h01;
        u.y = *(uint32_t*)&h23;
        dx[i] = u;
    }
}

// tiny dummy so the GEMM is the 4th launch in the stream (ncu -s alignment)
__global__ void dummy_kernel() { g_partials[0] = 0.f; }

// ----------------------------- GEMM ----------------------------------------
// smem: row-major [rows][64 halves] = 128B rows, 16B chunk c swizzled to
// c ^ (row & 7). cp.async stores and all ldmatrix phases conflict-free.
DINLINE void issue_stage(int kt, int fs, int tid, uint32_t sb,
                         const char* gA, const char* gB) {
    const uint32_t adst = sb + SMEM_A + fs * A_STAGE;
    const uint32_t bdst = sb + SMEM_B + fs * B_STAGE;
    const char* asrc = gA + kt * 128;
    const char* bsrc = gB + kt * 128;
    #pragma unroll
    for (int j = 0; j < 4; j++) {               // A: 1024 chunks
        int ci = tid + NTHREADS * j;
        int row = ci >> 3, c = ci & 7;
        cp_async16(adst + row * 128 + ((c ^ (row & 7)) << 4),
                   asrc + (size_t)row * 8192 + c * 16);
    }
    #pragma unroll
    for (int j = 0; j < 4; j++) {               // B: 1024 chunks
        int ci = tid + NTHREADS * j;
        int row = ci >> 3, c = ci & 7;
        cp_async16(bdst + row * 128 + ((c ^ (row & 7)) << 4),
                   bsrc + (size_t)row * 8192 + c * 16);
    }
}

// One K-tile. st = read stage (literal), pst = (st+1)%3 (literal).
// j0 fragments for THIS tile arrive preloaded in aa/bb; on exit aa/bb hold
// the j0 fragments of tile kt+1 (loaded after this tile's barrier).
DINLINE void tile_body(int kt, int st, int pst, int tid, uint32_t sb,
                       uint32_t aoff, uint32_t boff,
                       const char* gA, const char* gB,
                       uint32_t aa[2][4], uint32_t bb[4][4],
                       float acc[2][8][4]) {
    const uint32_t abase = sb + SMEM_A + st * A_STAGE + aoff;
    const uint32_t bbase = sb + SMEM_B + st * B_STAGE + boff;

    // j = 0 MMAs: fragments already in registers -> tensor pipe fires instantly
    #pragma unroll
    for (int mt = 0; mt < 2; mt++)
        #pragma unroll
        for (int nt = 0; nt < 8; nt++) {
            const int g = nt >> 1;
            if ((nt & 1) == 0) mma16816(acc[mt][nt], aa[mt], bb[g][0], bb[g][2]);
            else               mma16816(acc[mt][nt], aa[mt], bb[g][1], bb[g][3]);
        }

    // j = 1..3: ldsm + mma from this (visible) stage
    #pragma unroll
    for (int j = 1; j < 4; j++) {
        const uint32_t x = (uint32_t)(j << 5);
        #pragma unroll
        for (int mt = 0; mt < 2; mt++) ldsm4(aa[mt], (abase + mt * 2048) ^ x);
        #pragma unroll
        for (int nt = 0; nt < 4; nt++) ldsm4(bb[nt], (bbase + nt * 2048) ^ x);
        #pragma unroll
        for (int mt = 0; mt < 2; mt++)
            #pragma unroll
            for (int nt = 0; nt < 8; nt++) {
                const int g = nt >> 1;
                if ((nt & 1) == 0) mma16816(acc[mt][nt], aa[mt], bb[g][0], bb[g][2]);
                else               mma16816(acc[mt][nt], aa[mt], bb[g][1], bb[g][3]);
            }
    }

    // drain one group, sync, refill the stage we just finished reading (kt+3)
    CP_WAIT1();
    __syncthreads();
    if (kt + 3 < NKT) issue_stage(kt + 3, st, tid, sb, gA, gB);
    CP_COMMIT();

    // preload j0 fragments of tile kt+1 (stage pst: complete and visible)
    if (kt + 1 < NKT) {
        const uint32_t pa = sb + SMEM_A + pst * A_STAGE + aoff;
        const uint32_t pb = sb + SMEM_B + pst * B_STAGE + boff;
        #pragma unroll
        for (int mt = 0; mt < 2; mt++) ldsm4(aa[mt], pa + mt * 2048);
        #pragma unroll
        for (int nt = 0; nt < 4; nt++) ldsm4(bb[nt], pb + nt * 2048);
    }
}

__global__ void __launch_bounds__(NTHREADS, 2)
gemm_kernel(const float* __restrict__ bias, float* __restrict__ out) {
    extern __shared__ char smem[];
    const uint32_t sb = smem_u32(smem);
    const int tid = threadIdx.x, wid = tid >> 5, lid = tid & 31;

    // supertile mapping: 8 M-tiles x 128 N-tiles groups (8 groups of 1024)
    const int bid = blockIdx.x;
    const int grp = bid >> 10, rem = bid & 1023;
    const int mt_ = (grp << 3) | (rem & 7);
    const int nt_ = rem >> 3;
    const int m0 = mt_ * BM, n0 = nt_ * BN;

    const char* gA = (const char*)g_xh + (size_t)m0 * (KIN * 2);
    const char* gB = (const char*)g_tw + (size_t)n0 * (KIN * 2);

    // warp layout: 4 (M) x 2 (N), warp tile 32x64
    const int wm = wid & 3, wn = wid >> 2;

    // per-thread ldmatrix base offsets (swizzled, k-step 0)
    const int rlo = lid & 15, hh = lid >> 4;
    const int rowA = wm * 32 + rlo;
    const uint32_t aoff = (uint32_t)(rowA * 128 + ((hh ^ (rowA & 7)) << 4));
    const int rowB = wn * 64 + rlo;
    const uint32_t boff = (uint32_t)(rowB * 128 + ((hh ^ (rowB & 7)) << 4));

    float acc[2][8][4];
    #pragma unroll
    for (int i = 0; i < 2; i++)
        #pragma unroll
        for (int j = 0; j < 8; j++)
            #pragma unroll
            for (int q = 0; q < 4; q++) acc[i][j][q] = 0.f;

    // prologue: fill stages 0,1,2 (prefetch distance 3)
    issue_stage(0, 0, tid, sb, gA, gB); CP_COMMIT();
    issue_stage(1, 1, tid, sb, gA, gB); CP_COMMIT();
    issue_stage(2, 2, tid, sb, gA, gB); CP_COMMIT();

    // stages 0,1 complete; make them visible; preload tile 0's j0 fragments
    CP_WAIT1();
    __syncthreads();
    uint32_t aa[2][4], bb[4][4];
    #pragma unroll
    for (int mt = 0; mt < 2; mt++) ldsm4(aa[mt], sb + SMEM_A + aoff + mt * 2048);
    #pragma unroll
    for (int nt = 0; nt < 4; nt++) ldsm4(bb[nt], sb + SMEM_B + boff + nt * 2048);

    // 63 tiles = 21 triples with literal stage constants, then 1 tail tile.
    #pragma unroll 1
    for (int base = 0; base < NKT - 1; base += 3) {
        tile_body(base + 0, 0, 1, tid, sb, aoff, boff, gA, gB, aa, bb, acc);
        tile_body(base + 1, 1, 2, tid, sb, aoff, boff, gA, gB, aa, bb, acc);
        tile_body(base + 2, 2, 0, tid, sb, aoff, boff, gA, gB, aa, bb, acc);
    }
    tile_body(NKT - 1, 0, 1, tid, sb, aoff, boff, gA, gB, aa, bb, acc);  // kt=63

    // ----------------------------- epilogue --------------------------------
    const int rbase = m0 + wm * 32 + (lid >> 2);
    const int cbase = n0 + wn * 64 + (lid & 3) * 2;
    #pragma unroll
    for (int nt = 0; nt < 8; nt++) {
        const int col = cbase + nt * 8;
        const float2 bv = *(const float2*)(bias + col);
        #pragma unroll
        for (int mt = 0; mt < 2; mt++) {
            const int r0 = rbase + mt * 16;
            float2 v;
            v.x = acc[mt][nt][0] + bv.x;
            v.y = acc[mt][nt][1] + bv.y;
            *(float2*)(out + (size_t)r0 * NOUT + col) = v;
            v.x = acc[mt][nt][2] + bv.x;
            v.y = acc[mt][nt][3] + bv.y;
            *(float2*)(out + (size_t)(r0 + 8) * NOUT + col) = v;
        }
    }
}

// ----------------------------- launch --------------------------------------
extern "C" void kernel_launch(void* const* d_in, const int* in_sizes, int n_in,
                              void* d_out, int out_size) {
    const float* x    = (const float*)d_in[0];   // [8192, 4096]
    const float* w    = (const float*)d_in[1];   // [16384, 4096]
    const float* bias = (const float*)d_in[2];   // [16384]
    float* out        = (float*)d_out;           // [8192, 16384]

    cudaFuncSetAttribute(gemm_kernel, cudaFuncAttributeMaxDynamicSharedMemorySize, SMEM_BYTES);

    absum_kernel<<<2048, 256>>>(w);
    prep_kernel<<<4096, 256>>>(w, x);
    dummy_kernel<<<1, 1>>>();

    const int grid = (NROWS / BM) * (NOUT / BN);  // 64 * 128 = 8192
    gemm_kernel<<<grid, NTHREADS, SMEM_BYTES>>>(bias, out);
}